// round 1
// baseline (speedup 1.0000x reference)
#include <cuda_runtime.h>
#include <cstdint>
#include <cfloat>

// Problem constants (shapes fixed by the dataset)
#define NN    2048
#define TT    128
#define KSEL  20        // K = int(2048*0.01)
#define MAXA  20
#define LRC   0.01f
#define EPSC  1e-8f
#define NW32  (NN/32)   // 64 mask words per step

// ---------------- device scratch (no dynamic allocation allowed) ------------
__device__ __align__(16) static float    g_ST[(size_t)NN * NN];   // sigma^T, 16MB
__device__ static int16_t  g_act_idx[TT * MAXA];                  // active indices per step
__device__ static int      g_act_cnt[TT];                         // clamped count (<=MAXA)
__device__ static int      g_act_cntfull[TT];                     // true count (for ||x_next||)
__device__ static unsigned g_act_mask[TT * NW32];                 // bitmask per step
__device__ static int16_t  g_occ[NN * TT];                        // per-j list of steps s with j in A(s)
__device__ static int      g_occ_cnt[NN];

// ---------------- K1: top-K activation per token -----------------------------
// One block per t (128 blocks, 256 threads). Finds the K-th largest value of
// projection[token[t]] via K iterations of block-argmax, then builds mask+list.
__global__ void k_act(const int* __restrict__ tokens,
                      const float* __restrict__ proj) {
    const int t    = blockIdx.x;
    const int tid  = threadIdx.x;
    const int lane = tid & 31;
    const int w    = tid >> 5;
    const int base = tid * 8;

    __shared__ float    rv[8];
    __shared__ int      ri[8];
    __shared__ float    sb_thr;
    __shared__ int      sb_idx;
    __shared__ unsigned s_mask[NW32];
    __shared__ int      s_cnt;

    const float* row = proj + (size_t)tokens[t] * NN;
    const float4* rv4 = reinterpret_cast<const float4*>(row + base);
    float4 a = rv4[0], b = rv4[1];
    float v[8]    = {a.x, a.y, a.z, a.w, b.x, b.y, b.z, b.w};
    float orig[8] = {a.x, a.y, a.z, a.w, b.x, b.y, b.z, b.w};

    float thr = -FLT_MAX;
    for (int k = 0; k < KSEL; k++) {
        float bv = -FLT_MAX; int bi = 0;
        #pragma unroll
        for (int m = 0; m < 8; m++) {
            if (v[m] > bv) { bv = v[m]; bi = base + m; }
        }
        #pragma unroll
        for (int o = 16; o; o >>= 1) {
            float ov = __shfl_xor_sync(0xFFFFFFFFu, bv, o);
            int   oi = __shfl_xor_sync(0xFFFFFFFFu, bi, o);
            if (ov > bv) { bv = ov; bi = oi; }
        }
        if (lane == 0) { rv[w] = bv; ri[w] = bi; }
        __syncthreads();
        if (tid == 0) {
            float mv = rv[0]; int mi = ri[0];
            #pragma unroll
            for (int q = 1; q < 8; q++) if (rv[q] > mv) { mv = rv[q]; mi = ri[q]; }
            sb_thr = mv; sb_idx = mi;
        }
        __syncthreads();
        thr = sb_thr;
        const int widx = sb_idx;
        #pragma unroll
        for (int m = 0; m < 8; m++) {
            if (widx == base + m) v[m] = -FLT_MAX;
        }
        __syncthreads();
    }

    if (tid < NW32) s_mask[tid] = 0u;
    if (tid == 0)   s_cnt = 0;
    __syncthreads();

    #pragma unroll
    for (int m = 0; m < 8; m++) {
        if (orig[m] >= thr) {
            int i = base + m;
            atomicOr(&s_mask[i >> 5], 1u << (i & 31));
            int p = atomicAdd(&s_cnt, 1);
            if (p < MAXA) g_act_idx[t * MAXA + p] = (int16_t)i;
        }
    }
    __syncthreads();

    if (tid < NW32) g_act_mask[t * NW32 + tid] = s_mask[tid];
    if (tid == 0) {
        g_act_cntfull[t] = s_cnt;
        g_act_cnt[t]     = (s_cnt < MAXA) ? s_cnt : MAXA;
    }
}

// ---------------- K2: transpose sigma into g_ST ------------------------------
__global__ void k_transpose(const float* __restrict__ S) {
    __shared__ float tile[32][33];
    const int bx = blockIdx.x * 32, by = blockIdx.y * 32;
    int x = bx + threadIdx.x;
    #pragma unroll
    for (int r = 0; r < 32; r += 8) {
        int y = by + threadIdx.y + r;
        tile[threadIdx.y + r][threadIdx.x] = S[(size_t)y * NN + x];
    }
    __syncthreads();
    x = by + threadIdx.x;
    #pragma unroll
    for (int r = 0; r < 32; r += 8) {
        int y = bx + threadIdx.y + r;
        g_ST[(size_t)y * NN + x] = tile[threadIdx.x][threadIdx.y + r];
    }
}

// ---------------- K3: per-j occurrence lists ---------------------------------
// occ[j] = { s in [0, T-2] : j in A(s) }  (the x_curr steps)
__global__ void k_occ() {
    const int tid = threadIdx.x;
    for (int j = tid; j < NN; j += 256) g_occ_cnt[j] = 0;
    __syncthreads();
    for (int s = tid; s < TT - 1; s += 256) {
        const int c = g_act_cnt[s];
        for (int m = 0; m < c; m++) {
            const int j = g_act_idx[s * MAXA + m];
            const int pos = atomicAdd(&g_occ_cnt[j], 1);
            g_occ[j * TT + pos] = (int16_t)s;
        }
    }
}

// ---------------- K4: per-step tension (fully parallel over t) ---------------
// pred(t)[i] = sum_{j in A(t)} min(S0[i][j] + 0.01*c_t(i,j), 1)
//            = B[t][i] + corr(t)[i],  c_t from activation sets only.
__global__ void __launch_bounds__(256, 1)
k_main(const float* __restrict__ S0, const int* __restrict__ plast,
       float* __restrict__ out) {
    const int t    = blockIdx.x;       // 0..T-2
    const int tid  = threadIdx.x;      // 256 threads
    const int lane = tid & 31;
    const int w    = tid >> 5;
    const int i0   = tid * 8;

    __shared__ unsigned s_cntw[MAXA * NN / 4];  // 40960 B: packed byte counts
    __shared__ int16_t  s_idx[TT * MAXA];       // 5120 B
    __shared__ uint8_t  s_acnt[TT];             // 128 B
    __shared__ float    s_red[16];              // 64 B

    const int plasticity = *plast;

    for (int x = tid; x < TT * MAXA; x += 256) s_idx[x] = g_act_idx[x];
    for (int x = tid; x < TT; x += 256) s_acnt[x] = (uint8_t)g_act_cnt[x];
    if (plasticity) {
        for (int x = tid; x < MAXA * NN / 4; x += 256) s_cntw[x] = 0u;
    }
    __syncthreads();

    const int cnt_t = s_acnt[t];

    // phase 1: base pred B[t][i0..i0+7] from transposed sigma (coalesced)
    float p[8] = {0, 0, 0, 0, 0, 0, 0, 0};
    for (int js = 0; js < cnt_t; js++) {
        const int j = s_idx[t * MAXA + js];
        const float4* r = reinterpret_cast<const float4*>(g_ST + (size_t)j * NN + i0);
        float4 a = r[0], b = r[1];
        p[0] += a.x; p[1] += a.y; p[2] += a.z; p[3] += a.w;
        p[4] += b.x; p[5] += b.y; p[6] += b.z; p[7] += b.w;
    }

    if (plasticity) {
        // phase 2: count c_t(i,j) for j in A(t).
        // For each occurrence s<t of j in A(s), increment count for every i in A(s+1).
        for (int js = w; js < cnt_t; js += 8) {
            const int j  = s_idx[t * MAXA + js];
            const int oc = g_occ_cnt[j];
            for (int e = lane; e < oc; e += 32) {
                const int s = g_occ[j * TT + e];
                if (s < t) {
                    const int c2 = s_acnt[s + 1];
                    const int b2 = (s + 1) * MAXA;
                    for (int m = 0; m < c2; m++) {
                        const unsigned i = (unsigned)s_idx[b2 + m];
                        const unsigned off = (unsigned)(js * NN) + i;
                        atomicAdd(&s_cntw[off >> 2], 1u << ((off & 3u) * 8u));
                    }
                }
            }
        }
        __syncthreads();

        // phase 3: apply sparse corrections min(S0+0.01c,1)-S0
        for (int js = 0; js < cnt_t; js++) {
            const unsigned off = (unsigned)(js * NN) + (unsigned)i0;
            const unsigned w0 = s_cntw[off >> 2];
            const unsigned w1 = s_cntw[(off >> 2) + 1];
            if (w0 | w1) {
                const int j = s_idx[t * MAXA + js];
                #pragma unroll
                for (int m = 0; m < 4; m++) {
                    const unsigned c = (w0 >> (m * 8)) & 0xFFu;
                    if (c) {
                        const float v = S0[(size_t)(i0 + m) * NN + j];
                        p[m] += fminf(v + LRC * (float)c, 1.0f) - v;
                    }
                }
                #pragma unroll
                for (int m = 0; m < 4; m++) {
                    const unsigned c = (w1 >> (m * 8)) & 0xFFu;
                    if (c) {
                        const float v = S0[(size_t)(i0 + 4 + m) * NN + j];
                        p[4 + m] += fminf(v + LRC * (float)c, 1.0f) - v;
                    }
                }
            }
        }
    }

    // reduction: pn2 = sum pred^2 ; dot = sum_{i in A(t+1)} pred[i]
    const unsigned mword = g_act_mask[(t + 1) * NW32 + (i0 >> 5)];
    const unsigned mb = (mword >> (i0 & 31)) & 0xFFu;
    float pn2 = 0.0f, dt = 0.0f;
    #pragma unroll
    for (int m = 0; m < 8; m++) {
        pn2 += p[m] * p[m];
        if ((mb >> m) & 1u) dt += p[m];
    }
    #pragma unroll
    for (int o = 16; o; o >>= 1) {
        pn2 += __shfl_xor_sync(0xFFFFFFFFu, pn2, o);
        dt  += __shfl_xor_sync(0xFFFFFFFFu, dt, o);
    }
    __syncthreads();
    if (lane == 0) { s_red[2 * w] = pn2; s_red[2 * w + 1] = dt; }
    __syncthreads();
    if (tid == 0) {
        float P2 = 0.0f, D = 0.0f;
        #pragma unroll
        for (int q = 0; q < 8; q++) { P2 += s_red[2 * q]; D += s_red[2 * q + 1]; }
        const float pn = sqrtf(P2);
        float tension;
        if (plasticity) {
            const float overlap = D / (pn * sqrtf((float)KSEL) + EPSC);
            tension = (pn > 0.0f) ? (1.0f - overlap) : 1.0f;
        } else {
            const float xn = sqrtf((float)g_act_cntfull[t + 1]);
            tension = 1.0f - D / (pn * xn + EPSC);
        }
        out[t] = tension;
    }
}

// ---------------- launch -----------------------------------------------------
extern "C" void kernel_launch(void* const* d_in, const int* in_sizes, int n_in,
                              void* d_out, int out_size) {
    const int*   tokens = (const int*)d_in[0];
    const float* proj   = (const float*)d_in[1];
    const float* sigma  = (const float*)d_in[2];
    const int*   plast  = (const int*)d_in[3];
    float*       out    = (float*)d_out;

    k_act<<<TT, 256>>>(tokens, proj);
    k_transpose<<<dim3(NN / 32, NN / 32), dim3(32, 8)>>>(sigma);
    k_occ<<<1, 256>>>();
    k_main<<<TT - 1, 256>>>(sigma, plast, out);
}

// round 2
// speedup vs baseline: 1.5183x; 1.5183x over previous
#include <cuda_runtime.h>
#include <cstdint>
#include <cfloat>

// Problem constants (fixed by dataset)
#define NN    2048
#define TT    128
#define KSEL  20
#define MAXA  20
#define LRC   0.01f
#define EPSC  1e-8f
#define NW32  (NN/32)
#define QSPL  4            // i-range splits per step in k_main
#define ISEG  (NN/QSPL)    // 512

// ---------------- device scratch ---------------------------------------------
__device__ __align__(16) static float    g_ST[(size_t)NN * NN];   // sigma^T
__device__ static int16_t  g_act_idx[TT * MAXA];
__device__ static int      g_act_cnt[TT];
__device__ static int      g_act_cntfull[TT];
__device__ static unsigned g_act_mask[TT * NW32];
__device__ static float    g_part[(TT - 1) * QSPL * 2];           // per-slot partials
__device__ static int      g_done[TT - 1];

// ================= K_prep: transpose (blocks 0..4095) + top-K (4096..4223) ===
__global__ void __launch_bounds__(256)
k_prep(const int* __restrict__ tokens, const float* __restrict__ proj,
       const float* __restrict__ S) {
    const int bx  = blockIdx.x;
    const int tid = threadIdx.x;

    if (bx < (NN / 32) * (NN / 32)) {
        // -------- transpose 32x32 tile --------
        __shared__ float tile[32][33];
        const int tx = tid & 31, ty = tid >> 5;            // ty in 0..7
        const int bi = bx & (NN / 32 - 1), bj = bx >> 6;
        const int x0 = bi * 32, y0 = bj * 32;
        int x = x0 + tx;
        #pragma unroll
        for (int r = 0; r < 32; r += 8)
            tile[ty + r][tx] = S[(size_t)(y0 + ty + r) * NN + x];
        __syncthreads();
        x = y0 + tx;
        #pragma unroll
        for (int r = 0; r < 32; r += 8)
            g_ST[(size_t)(x0 + ty + r) * NN + x] = tile[tx][ty + r];
        return;
    }

    // -------- top-K via 4-pass radix select (one block per token) --------
    const int t    = bx - (NN / 32) * (NN / 32);
    const int lane = tid & 31;
    const int base = tid * 8;

    __shared__ unsigned hist[256];
    __shared__ unsigned s_prefix;
    __shared__ int      s_kk;
    __shared__ unsigned s_mask[NW32];
    __shared__ int      s_cnt;

    const float* row = proj + (size_t)tokens[t] * NN;
    const float4* rv4 = reinterpret_cast<const float4*>(row + base);
    float4 a = rv4[0], b = rv4[1];
    float v[8] = {a.x, a.y, a.z, a.w, b.x, b.y, b.z, b.w};
    unsigned key[8];
    #pragma unroll
    for (int m = 0; m < 8; m++) {
        unsigned u = __float_as_uint(v[m]);
        key[m] = (u >> 31) ? ~u : (u | 0x80000000u);       // monotonic map
    }

    if (tid == 0) { s_prefix = 0u; s_kk = KSEL; }
    unsigned prefix = 0u;
    int kk = KSEL;

    #pragma unroll
    for (int bp = 3; bp >= 0; bp--) {
        hist[tid] = 0u;
        __syncthreads();
        #pragma unroll
        for (int m = 0; m < 8; m++) {
            bool match = (bp == 3) || ((key[m] >> ((bp + 1) * 8)) == prefix);
            if (match) atomicAdd(&hist[(key[m] >> (bp * 8)) & 0xFFu], 1u);
        }
        __syncthreads();
        if (tid < 32) {
            // lane l owns 8 bins, descending chunks: lane0 = bins 255..248
            const int top = 255 - lane * 8;
            unsigned local = 0;
            unsigned hv[8];
            #pragma unroll
            for (int q = 0; q < 8; q++) { hv[q] = hist[top - q]; local += hv[q]; }
            unsigned incl = local;
            #pragma unroll
            for (int o = 1; o < 32; o <<= 1) {
                unsigned u = __shfl_up_sync(0xFFFFFFFFu, incl, o);
                if (lane >= o) incl += u;
            }
            unsigned excl = incl - local;
            if (excl < (unsigned)kk && incl >= (unsigned)kk) {
                unsigned e = excl;
                #pragma unroll
                for (int q = 0; q < 8; q++) {
                    if (e + hv[q] >= (unsigned)kk) {
                        s_prefix = (prefix << 8) | (unsigned)(top - q);
                        s_kk = kk - (int)e;
                        break;
                    }
                    e += hv[q];
                }
            }
        }
        __syncthreads();
        prefix = s_prefix;
        kk = s_kk;
    }
    const unsigned key_thr = prefix;

    if (tid < NW32) s_mask[tid] = 0u;
    if (tid == 0)   s_cnt = 0;
    __syncthreads();

    #pragma unroll
    for (int m = 0; m < 8; m++) {
        if (key[m] >= key_thr) {
            int i = base + m;
            atomicOr(&s_mask[i >> 5], 1u << (i & 31));
            int p = atomicAdd(&s_cnt, 1);
            if (p < MAXA) g_act_idx[t * MAXA + p] = (int16_t)i;
        }
    }
    __syncthreads();

    if (tid < NW32) g_act_mask[t * NW32 + tid] = s_mask[tid];
    if (tid == 0) {
        g_act_cntfull[t] = s_cnt;
        g_act_cnt[t]     = (s_cnt < MAXA) ? s_cnt : MAXA;
        if (t < TT - 1) g_done[t] = 0;                     // reset combine counter
    }
}

// ================= K_main: 4 CTAs per step t, i-segment of 512 each ==========
__global__ void __launch_bounds__(256)
k_main(const float* __restrict__ S0, const int* __restrict__ plast,
       float* __restrict__ out) {
    const int bx   = blockIdx.x;
    const int t    = bx >> 2;          // 0..126
    const int q    = bx & 3;
    const int lo   = q * ISEG;
    const int tid  = threadIdx.x;
    const int lane = tid & 31;
    const int w    = tid >> 5;
    const int i0   = lo + tid * 2;

    __shared__ unsigned s_cntw[MAXA * ISEG / 4];   // 10240 B packed byte counts
    __shared__ int16_t  s_idx[TT * MAXA];          // 5120 B
    __shared__ uint8_t  s_acnt[TT];
    __shared__ uint8_t  s_pos[NN];                 // j -> js (0xFF = not in A(t))
    __shared__ float    s_red[16];

    const int plasticity = *plast;

    for (int x = tid; x < TT * MAXA / 2; x += 256)
        reinterpret_cast<int*>(s_idx)[x] = reinterpret_cast<const int*>(g_act_idx)[x];
    for (int x = tid; x < TT; x += 256) s_acnt[x] = (uint8_t)g_act_cnt[x];
    for (int x = tid; x < NN / 4; x += 256)
        reinterpret_cast<unsigned*>(s_pos)[x] = 0xFFFFFFFFu;
    if (plasticity)
        for (int x = tid; x < MAXA * ISEG / 4; x += 256) s_cntw[x] = 0u;
    __syncthreads();

    const int cnt_t = s_acnt[t];
    if (tid < cnt_t) s_pos[(int)s_idx[t * MAXA + tid]] = (uint8_t)tid;
    __syncthreads();

    // phase 1: base pred over this i-segment (coalesced rows of sigma^T)
    float p0 = 0.f, p1 = 0.f;
    for (int js = 0; js < cnt_t; js++) {
        const int j = s_idx[t * MAXA + js];
        const float2 r = *reinterpret_cast<const float2*>(g_ST + (size_t)j * NN + i0);
        p0 += r.x; p1 += r.y;
    }

    if (plasticity) {
        // phase 2: counts c_t(i,j) via direct scan of s < t
        for (int wk = tid; wk < t * MAXA; wk += 256) {
            const int s = wk / MAXA;
            const int m = wk - s * MAXA;
            if (m < s_acnt[s]) {
                const int j  = s_idx[s * MAXA + m];
                const int js = s_pos[j];
                if (js != 0xFF) {
                    const int c2 = s_acnt[s + 1];
                    const int b2 = (s + 1) * MAXA;
                    for (int mm = 0; mm < c2; mm++) {
                        const int i = s_idx[b2 + mm];
                        const unsigned d = (unsigned)(i - lo);
                        if (d < (unsigned)ISEG) {
                            const unsigned off = (unsigned)js * ISEG + d;
                            atomicAdd(&s_cntw[off >> 2], 1u << ((off & 3u) * 8u));
                        }
                    }
                }
            }
        }
        __syncthreads();

        // phase 3: sparse clip corrections
        for (int js = 0; js < cnt_t; js++) {
            const unsigned off = (unsigned)js * ISEG + (unsigned)(tid * 2);
            const unsigned word = s_cntw[off >> 2];
            const unsigned two  = (word >> ((off & 3u) * 8u)) & 0xFFFFu;
            if (two) {
                const int j = s_idx[t * MAXA + js];
                const unsigned c0 = two & 0xFFu, c1 = (two >> 8) & 0xFFu;
                if (c0) {
                    const float v = S0[(size_t)i0 * NN + j];
                    p0 += fminf(v + LRC * (float)c0, 1.0f) - v;
                }
                if (c1) {
                    const float v = S0[(size_t)(i0 + 1) * NN + j];
                    p1 += fminf(v + LRC * (float)c1, 1.0f) - v;
                }
            }
        }
    }

    // reduction over segment: pn2 partial, dot partial
    const unsigned mword = g_act_mask[(t + 1) * NW32 + (i0 >> 5)];
    float pn2 = p0 * p0 + p1 * p1;
    float dt  = 0.f;
    if ((mword >> (i0 & 31)) & 1u)       dt += p0;
    if ((mword >> ((i0 + 1) & 31)) & 1u) dt += p1;
    #pragma unroll
    for (int o = 16; o; o >>= 1) {
        pn2 += __shfl_xor_sync(0xFFFFFFFFu, pn2, o);
        dt  += __shfl_xor_sync(0xFFFFFFFFu, dt, o);
    }
    if (lane == 0) { s_red[2 * w] = pn2; s_red[2 * w + 1] = dt; }
    __syncthreads();

    if (tid == 0) {
        float P2 = 0.f, D = 0.f;
        #pragma unroll
        for (int r = 0; r < 8; r++) { P2 += s_red[2 * r]; D += s_red[2 * r + 1]; }
        g_part[(t * QSPL + q) * 2 + 0] = P2;
        g_part[(t * QSPL + q) * 2 + 1] = D;
        __threadfence();
        const int d = atomicAdd(&g_done[t], 1);
        if (d == QSPL - 1) {
            __threadfence();
            float TP2 = 0.f, TD = 0.f;
            #pragma unroll
            for (int s = 0; s < QSPL; s++) {
                TP2 += g_part[(t * QSPL + s) * 2 + 0];
                TD  += g_part[(t * QSPL + s) * 2 + 1];
            }
            const float pn = sqrtf(TP2);
            float tension;
            if (plasticity) {
                const float overlap = TD / (pn * sqrtf((float)KSEL) + EPSC);
                tension = (pn > 0.0f) ? (1.0f - overlap) : 1.0f;
            } else {
                const float xn = sqrtf((float)g_act_cntfull[t + 1]);
                tension = 1.0f - TD / (pn * xn + EPSC);
            }
            out[t] = tension;
        }
    }
}

// ---------------- launch ------------------------------------------------------
extern "C" void kernel_launch(void* const* d_in, const int* in_sizes, int n_in,
                              void* d_out, int out_size) {
    const int*   tokens = (const int*)d_in[0];
    const float* proj   = (const float*)d_in[1];
    const float* sigma  = (const float*)d_in[2];
    const int*   plast  = (const int*)d_in[3];
    float*       out    = (float*)d_out;

    k_prep<<<(NN / 32) * (NN / 32) + TT, 256>>>(tokens, proj, sigma);
    k_main<<<(TT - 1) * QSPL, 256>>>(sigma, plast, out);
}